// round 3
// baseline (speedup 1.0000x reference)
#include <cuda_runtime.h>
#include <cuda_fp16.h>
#include <stdint.h>

#define D_MODEL  1024
#define D_HIDDEN 4096
#define NE       16
#define BTOK     32768
#define CAP      2560

// ---------------- device scratch (static, no allocations) ----------------
static __device__ __half g_xh  [(size_t)BTOK * D_MODEL];                 // 64 MB
static __device__ __half g_w1h [(size_t)NE * D_MODEL * D_HIDDEN];        // 128 MB
static __device__ __half g_w2h [(size_t)NE * D_HIDDEN * D_MODEL];        // 128 MB
static __device__ __half g_hbuf[(size_t)NE * CAP * D_HIDDEN];            // 320 MB
static __device__ int    g_eid[BTOK];
static __device__ float  g_score[BTOK];
static __device__ int    g_counts[NE];
static __device__ int    g_fill[NE];
static __device__ int    g_list[NE * CAP];

// ---------------- small kernels ----------------
__global__ void zero_counts_kernel() {
    if (threadIdx.x < NE) { g_counts[threadIdx.x] = 0; g_fill[threadIdx.x] = 0; }
}

__global__ void cvt_w1_kernel(const float4* __restrict__ src) {
    __half2* dst = (__half2*)g_w1h;
    const int n4 = NE * D_MODEL * (D_HIDDEN / 4);
    for (int i = blockIdx.x * blockDim.x + threadIdx.x; i < n4; i += gridDim.x * blockDim.x) {
        float4 v = src[i];
        dst[2 * i + 0] = __floats2half2_rn(v.x, v.y);
        dst[2 * i + 1] = __floats2half2_rn(v.z, v.w);
    }
}
__global__ void cvt_w2_kernel(const float4* __restrict__ src) {
    __half2* dst = (__half2*)g_w2h;
    const int n4 = NE * D_MODEL * (D_HIDDEN / 4);
    for (int i = blockIdx.x * blockDim.x + threadIdx.x; i < n4; i += gridDim.x * blockDim.x) {
        float4 v = src[i];
        dst[2 * i + 0] = __floats2half2_rn(v.x, v.y);
        dst[2 * i + 1] = __floats2half2_rn(v.z, v.w);
    }
}

// one warp per token: fp32 logits (routing must match reference argmax),
// fp16 copy of x written as a side effect.
__global__ void gating_kernel(const float* __restrict__ x, const float* __restrict__ gw) {
    extern __shared__ float s_gw[];   // 16 x 1024 fp32 = 64 KB
    for (int i = threadIdx.x; i < NE * D_MODEL; i += blockDim.x) s_gw[i] = gw[i];
    __syncthreads();

    const int warp = threadIdx.x >> 5, lane = threadIdx.x & 31;
    const int t = blockIdx.x * 8 + warp;
    const float* xr = x + (size_t)t * D_MODEL;

    float acc[NE];
#pragma unroll
    for (int e = 0; e < NE; ++e) acc[e] = 0.f;

#pragma unroll 4
    for (int it = 0; it < D_MODEL / 32; ++it) {
        int d = it * 32 + lane;
        float xv = xr[d];
        g_xh[(size_t)t * D_MODEL + d] = __float2half_rn(xv);
#pragma unroll
        for (int e = 0; e < NE; ++e) acc[e] += xv * s_gw[e * D_MODEL + d];
    }
#pragma unroll
    for (int e = 0; e < NE; ++e)
#pragma unroll
        for (int o = 16; o > 0; o >>= 1) acc[e] += __shfl_xor_sync(0xffffffffu, acc[e], o);

    if (lane == 0) {
        float mx = acc[0]; int am = 0;
#pragma unroll
        for (int e = 1; e < NE; ++e) if (acc[e] > mx) { mx = acc[e]; am = e; }
        float s = 0.f;
#pragma unroll
        for (int e = 0; e < NE; ++e) s += expf(acc[e] - mx);
        g_score[t] = 1.f / s;
        g_eid[t]   = am;
        atomicAdd(&g_counts[am], 1);
    }
}

__global__ void build_list_kernel() {
    int t = blockIdx.x * blockDim.x + threadIdx.x;
    if (t >= BTOK) return;
    int e = g_eid[t];
    int p = atomicAdd(&g_fill[e], 1);
    if (p < CAP) g_list[e * CAP + p] = t;
}

__global__ void stats_kernel(float* __restrict__ out, long long out_size) {
    int e = threadIdx.x;
    float c  = (e < NE) ? (float)g_counts[e] : 0.f;
    const float expc = (float)BTOK / NE;     // 2048
    float d  = (e < NE) ? (c - expc) * (c - expc) : 0.f;
    float ov = (e < NE) ? fmaxf(c - (float)CAP, 0.f) : 0.f;
#pragma unroll
    for (int o = 16; o > 0; o >>= 1) {
        d  += __shfl_xor_sync(0xffffffffu, d,  o);
        ov += __shfl_xor_sync(0xffffffffu, ov, o);
    }
    if (threadIdx.x == 0) {
        float lb = (d / NE) / (expc * expc);
        if (out_size > (long long)BTOK * D_MODEL)     out[(long long)BTOK * D_MODEL]     = lb;
        if (out_size > (long long)BTOK * D_MODEL + 1) out[(long long)BTOK * D_MODEL + 1] = ov / (float)BTOK;
    }
}

// ---------------- mma helpers ----------------
__device__ __forceinline__ void ldsm4(uint32_t& r0, uint32_t& r1, uint32_t& r2, uint32_t& r3,
                                      const void* p) {
    uint32_t a = (uint32_t)__cvta_generic_to_shared(p);
    asm volatile("ldmatrix.sync.aligned.m8n8.x4.shared.b16 {%0,%1,%2,%3},[%4];"
                 : "=r"(r0), "=r"(r1), "=r"(r2), "=r"(r3) : "r"(a));
}
__device__ __forceinline__ void ldsm4t(uint32_t& r0, uint32_t& r1, uint32_t& r2, uint32_t& r3,
                                       const void* p) {
    uint32_t a = (uint32_t)__cvta_generic_to_shared(p);
    asm volatile("ldmatrix.sync.aligned.m8n8.x4.trans.shared.b16 {%0,%1,%2,%3},[%4];"
                 : "=r"(r0), "=r"(r1), "=r"(r2), "=r"(r3) : "r"(a));
}
__device__ __forceinline__ void mma16816(float* c, const uint32_t* a, const uint32_t* b) {
    asm volatile("mma.sync.aligned.m16n8k16.row.col.f32.f16.f16.f32 "
                 "{%0,%1,%2,%3},{%4,%5,%6,%7},{%8,%9},{%0,%1,%2,%3};"
                 : "+f"(c[0]), "+f"(c[1]), "+f"(c[2]), "+f"(c[3])
                 : "r"(a[0]), "r"(a[1]), "r"(a[2]), "r"(a[3]), "r"(b[0]), "r"(b[1]));
}
__device__ __forceinline__ float gelu_tanh(float v) {
    float v3 = v * v * v;
    return 0.5f * v * (1.f + tanhf(0.7978845608028654f * (v + 0.044715f * v3)));
}

// ---------------- FFN GEMMs ----------------
// MODE 0: H = gelu(gather(x_h) @ W1[e] + b1[e])   -> g_hbuf (fp16)   N=4096 K=1024
// MODE 1: ye = g_hbuf[e] @ W2[e] + b2[e]          -> out[token]      N=1024 K=4096
template <int MODE>
__global__ void moe_ffn_kernel(const float* __restrict__ bias, float* __restrict__ out) {
    constexpr int N  = (MODE == 0) ? D_HIDDEN : D_MODEL;
    constexpr int K  = (MODE == 0) ? D_MODEL  : D_HIDDEN;
    constexpr int NK = K / 32;

    const int e  = blockIdx.z;
    const int m0 = blockIdx.y * 128;
    const int n0 = blockIdx.x * 128;
    const int me = min(g_counts[e], CAP);
    if (m0 >= me) return;

    __shared__ __half sA[128][40];
    __shared__ __half sB[32][136];
    __shared__ int    s_tok[128];

    const int tid = threadIdx.x;
    if (tid < 128) {
        int slot = m0 + tid;
        s_tok[tid] = (slot < me) ? g_list[e * CAP + slot] : -1;
    }
    __syncthreads();

    const __half* Bsrc = ((MODE == 0) ? g_w1h : g_w2h) + (size_t)e * D_MODEL * D_HIDDEN;

    // per-thread load geometry
    const int arow0 = tid >> 2, ac = (tid & 3) * 8;          // A: 128x32, 2 uint4/thread
    const int brow0 = tid >> 4, bc = (tid & 15) * 8;         // B:  32x128, 2 uint4/thread
    const __half* aP0;
    const __half* aP1;
    if (MODE == 0) {
        int t0 = s_tok[arow0], t1 = s_tok[arow0 + 64];
        aP0 = (t0 >= 0) ? g_xh + (size_t)t0 * D_MODEL + ac : (const __half*)0;
        aP1 = (t1 >= 0) ? g_xh + (size_t)t1 * D_MODEL + ac : (const __half*)0;
    } else {
        const __half* base = g_hbuf + (size_t)e * CAP * D_HIDDEN;
        aP0 = base + (size_t)(m0 + arow0)      * D_HIDDEN + ac;
        aP1 = base + (size_t)(m0 + arow0 + 64) * D_HIDDEN + ac;
    }
    const __half* bP0 = Bsrc + (size_t)brow0 * N + n0 + bc;
    const __half* bP1 = bP0 + (size_t)16 * N;

    const int wid = tid >> 5, lane = tid & 31;
    const int wr = wid & 1, wc = wid >> 1;          // warp tile: 64 rows x 32 cols
    const int lrow = lane & 15, lkh = (lane >> 4) << 3;

    float acc[4][4][4];
#pragma unroll
    for (int mi = 0; mi < 4; ++mi)
#pragma unroll
        for (int nj = 0; nj < 4; ++nj)
#pragma unroll
            for (int q = 0; q < 4; ++q) acc[mi][nj][q] = 0.f;

    const uint4 z4 = make_uint4(0u, 0u, 0u, 0u);
    uint4 pa0 = aP0 ? *(const uint4*)(aP0) : z4;
    uint4 pa1 = aP1 ? *(const uint4*)(aP1) : z4;
    uint4 pb0 = *(const uint4*)(bP0);
    uint4 pb1 = *(const uint4*)(bP1);

#pragma unroll 1
    for (int kt = 0; kt < NK; ++kt) {
        *(uint4*)&sA[arow0][ac]      = pa0;
        *(uint4*)&sA[arow0 + 64][ac] = pa1;
        *(uint4*)&sB[brow0][bc]      = pb0;
        *(uint4*)&sB[brow0 + 16][bc] = pb1;
        __syncthreads();

        if (kt + 1 < NK) {
            const int ko = (kt + 1) * 32;
            pa0 = aP0 ? *(const uint4*)(aP0 + ko) : z4;
            pa1 = aP1 ? *(const uint4*)(aP1 + ko) : z4;
            pb0 = *(const uint4*)(bP0 + (size_t)ko * N);
            pb1 = *(const uint4*)(bP1 + (size_t)ko * N);
        }

#pragma unroll
        for (int kk = 0; kk < 2; ++kk) {
            const int ks = kk * 16;
            uint32_t af[4][4];
#pragma unroll
            for (int mi = 0; mi < 4; ++mi)
                ldsm4(af[mi][0], af[mi][1], af[mi][2], af[mi][3],
                      &sA[wr * 64 + mi * 16 + lrow][ks + lkh]);
            uint32_t bf[4][2];
#pragma unroll
            for (int nq = 0; nq < 2; ++nq) {
                uint32_t r0, r1, r2, r3;
                ldsm4t(r0, r1, r2, r3, &sB[ks + lrow][wc * 32 + nq * 16 + lkh]);
                bf[nq * 2][0] = r0; bf[nq * 2][1] = r1;
                bf[nq * 2 + 1][0] = r2; bf[nq * 2 + 1][1] = r3;
            }
#pragma unroll
            for (int mi = 0; mi < 4; ++mi)
#pragma unroll
                for (int nj = 0; nj < 4; ++nj)
                    mma16816(acc[mi][nj], af[mi], bf[nj]);
        }
        __syncthreads();
    }

    // epilogue
#pragma unroll
    for (int mi = 0; mi < 4; ++mi) {
        const int r0 = wr * 64 + mi * 16 + (lane >> 2);
#pragma unroll
        for (int nj = 0; nj < 4; ++nj) {
            const int col = n0 + wc * 32 + nj * 8 + (lane & 3) * 2;
            if (MODE == 0) {
                float bb0 = bias[e * D_HIDDEN + col];
                float bb1 = bias[e * D_HIDDEN + col + 1];
                float v0 = gelu_tanh(acc[mi][nj][0] + bb0);
                float v1 = gelu_tanh(acc[mi][nj][1] + bb1);
                float v2 = gelu_tanh(acc[mi][nj][2] + bb0);
                float v3 = gelu_tanh(acc[mi][nj][3] + bb1);
                __half* hb = g_hbuf + (size_t)e * CAP * D_HIDDEN;
                *(__half2*)(hb + (size_t)(m0 + r0)     * D_HIDDEN + col) = __floats2half2_rn(v0, v1);
                *(__half2*)(hb + (size_t)(m0 + r0 + 8) * D_HIDDEN + col) = __floats2half2_rn(v2, v3);
            } else {
                float bb0 = bias[e * D_MODEL + col];
                float bb1 = bias[e * D_MODEL + col + 1];
                int tok0 = s_tok[r0], tok1 = s_tok[r0 + 8];
                if (tok0 >= 0) {
                    float2 v; v.x = acc[mi][nj][0] + bb0; v.y = acc[mi][nj][1] + bb1;
                    *(float2*)(out + (size_t)tok0 * D_MODEL + col) = v;
                }
                if (tok1 >= 0) {
                    float2 v; v.x = acc[mi][nj][2] + bb0; v.y = acc[mi][nj][3] + bb1;
                    *(float2*)(out + (size_t)tok1 * D_MODEL + col) = v;
                }
            }
        }
    }
}

// ---------------- launch ----------------
extern "C" void kernel_launch(void* const* d_in, const int* in_sizes, int n_in,
                              void* d_out, int out_size) {
    const float* x    = (const float*)d_in[0];
    const float* gw   = (const float*)d_in[1];
    const float* w1   = (const float*)d_in[2];
    const float* b1   = (const float*)d_in[3];
    const float* w2   = (const float*)d_in[4];
    const float* b2   = (const float*)d_in[5];
    float*       out  = (float*)d_out;

    zero_counts_kernel<<<1, 32>>>();
    cvt_w1_kernel<<<2048, 256>>>((const float4*)w1);
    cvt_w2_kernel<<<2048, 256>>>((const float4*)w2);

    cudaFuncSetAttribute(gating_kernel, cudaFuncAttributeMaxDynamicSharedMemorySize, 65536);
    gating_kernel<<<BTOK / 8, 256, 65536>>>(x, gw);

    build_list_kernel<<<BTOK / 256, 256>>>();
    stats_kernel<<<1, 32>>>(out, (long long)out_size);

    // default: y = x (routed rows overwritten by GEMM2)
    cudaMemcpyAsync(d_out, (const void*)x, (size_t)BTOK * D_MODEL * sizeof(float),
                    cudaMemcpyDeviceToDevice);

    moe_ffn_kernel<0><<<dim3(D_HIDDEN / 128, CAP / 128, NE), 256>>>(b1, out);
    moe_ffn_kernel<1><<<dim3(D_MODEL / 128, CAP / 128, NE), 256>>>(b2, out);
}

// round 6
// speedup vs baseline: 1.0321x; 1.0321x over previous
#include <cuda_runtime.h>
#include <cuda_fp16.h>
#include <stdint.h>

#define D_MODEL  1024
#define D_HIDDEN 4096
#define NE       16
#define BTOK     32768
#define CAP      2560

// GEMM tiling
#define TM   128
#define TN   256
#define TK   32
#define NSTG 4
#define SA_HALVES 40            // padded row stride for A tile (128 x 32)
#define SB_HALVES 264           // padded row stride for B tile (32 x 256)
#define SA_BYTES  (128 * SA_HALVES * 2)   // 10240
#define SB_BYTES  (TK * SB_HALVES * 2)    // 16896
#define STG_BYTES (SA_BYTES + SB_BYTES)   // 27136
#define SMEM_TOTAL (NSTG * STG_BYTES)     // 108544

static __device__ __align__(256) __half g_xh  [(size_t)BTOK * D_MODEL];
static __device__ __align__(256) __half g_w1h [(size_t)NE * D_MODEL * D_HIDDEN];
static __device__ __align__(256) __half g_w2h [(size_t)NE * D_HIDDEN * D_MODEL];
static __device__ __align__(256) __half g_hbuf[(size_t)NE * CAP * D_HIDDEN];
static __device__ int g_eid[BTOK];
static __device__ int g_counts[NE];
static __device__ int g_fill[NE];
static __device__ int g_list[NE * CAP];

// ---------------- small kernels ----------------
__global__ void zero_counts_kernel() {
    if (threadIdx.x < NE) { g_counts[threadIdx.x] = 0; g_fill[threadIdx.x] = 0; }
}

__global__ void cvt_w1_kernel(const float4* __restrict__ src) {
    __half2* dst = (__half2*)g_w1h;
    const int n4 = NE * D_MODEL * (D_HIDDEN / 4);
    for (int i = blockIdx.x * blockDim.x + threadIdx.x; i < n4; i += gridDim.x * blockDim.x) {
        float4 v = src[i];
        dst[2 * i + 0] = __floats2half2_rn(v.x, v.y);
        dst[2 * i + 1] = __floats2half2_rn(v.z, v.w);
    }
}
__global__ void cvt_w2_kernel(const float4* __restrict__ src) {
    __half2* dst = (__half2*)g_w2h;
    const int n4 = NE * D_MODEL * (D_HIDDEN / 4);
    for (int i = blockIdx.x * blockDim.x + threadIdx.x; i < n4; i += gridDim.x * blockDim.x) {
        float4 v = src[i];
        dst[2 * i + 0] = __floats2half2_rn(v.x, v.y);
        dst[2 * i + 1] = __floats2half2_rn(v.z, v.w);
    }
}

// one warp per token, float4 loads; fp32 logits (argmax must match reference);
// writes fp16 copy of x as a side effect.
__global__ void gating_kernel(const float4* __restrict__ x4, const float4* __restrict__ gw4) {
    extern __shared__ float4 sgw[];   // 16 x 256 float4 = 64 KB
    for (int i = threadIdx.x; i < NE * (D_MODEL / 4); i += blockDim.x) sgw[i] = gw4[i];
    __syncthreads();

    const int warp = threadIdx.x >> 5, lane = threadIdx.x & 31;
    const int t = blockIdx.x * 8 + warp;
    const float4* xr = x4 + (size_t)t * (D_MODEL / 4);
    __half2* xo = (__half2*)g_xh + (size_t)t * (D_MODEL / 2);

    float acc[NE];
#pragma unroll
    for (int e = 0; e < NE; ++e) acc[e] = 0.f;
#pragma unroll
    for (int i = 0; i < 8; ++i) {
        int d = i * 32 + lane;
        float4 xv = xr[d];
        xo[d * 2 + 0] = __floats2half2_rn(xv.x, xv.y);
        xo[d * 2 + 1] = __floats2half2_rn(xv.z, xv.w);
#pragma unroll
        for (int e = 0; e < NE; ++e) {
            float4 g = sgw[e * (D_MODEL / 4) + d];
            acc[e] += xv.x * g.x + xv.y * g.y + xv.z * g.z + xv.w * g.w;
        }
    }
#pragma unroll
    for (int e = 0; e < NE; ++e)
#pragma unroll
        for (int o = 16; o > 0; o >>= 1) acc[e] += __shfl_xor_sync(0xffffffffu, acc[e], o);

    if (lane == 0) {
        float mx = acc[0]; int am = 0;
#pragma unroll
        for (int e = 1; e < NE; ++e) if (acc[e] > mx) { mx = acc[e]; am = e; }
        g_eid[t] = am;
        atomicAdd(&g_counts[am], 1);
    }
}

__global__ void build_list_kernel() {
    int t = blockIdx.x * blockDim.x + threadIdx.x;
    if (t >= BTOK) return;
    int e = g_eid[t];
    int p = atomicAdd(&g_fill[e], 1);
    if (p < CAP) g_list[e * CAP + p] = t;
}

__global__ void stats_kernel(float* __restrict__ out, long long out_size) {
    int e = threadIdx.x;
    float c  = (e < NE) ? (float)g_counts[e] : 0.f;
    const float expc = (float)BTOK / NE;
    float d  = (e < NE) ? (c - expc) * (c - expc) : 0.f;
    float ov = (e < NE) ? fmaxf(c - (float)CAP, 0.f) : 0.f;
#pragma unroll
    for (int o = 16; o > 0; o >>= 1) {
        d  += __shfl_xor_sync(0xffffffffu, d,  o);
        ov += __shfl_xor_sync(0xffffffffu, ov, o);
    }
    if (threadIdx.x == 0) {
        float lb = (d / NE) / (expc * expc);
        if (out_size > (long long)BTOK * D_MODEL)     out[(long long)BTOK * D_MODEL]     = lb;
        if (out_size > (long long)BTOK * D_MODEL + 1) out[(long long)BTOK * D_MODEL + 1] = ov / (float)BTOK;
    }
}

// ---------------- mma helpers ----------------
__device__ __forceinline__ void ldsm4(uint32_t& r0, uint32_t& r1, uint32_t& r2, uint32_t& r3,
                                      const void* p) {
    uint32_t a = (uint32_t)__cvta_generic_to_shared(p);
    asm volatile("ldmatrix.sync.aligned.m8n8.x4.shared.b16 {%0,%1,%2,%3},[%4];"
                 : "=r"(r0), "=r"(r1), "=r"(r2), "=r"(r3) : "r"(a));
}
__device__ __forceinline__ void ldsm4t(uint32_t& r0, uint32_t& r1, uint32_t& r2, uint32_t& r3,
                                       const void* p) {
    uint32_t a = (uint32_t)__cvta_generic_to_shared(p);
    asm volatile("ldmatrix.sync.aligned.m8n8.x4.trans.shared.b16 {%0,%1,%2,%3},[%4];"
                 : "=r"(r0), "=r"(r1), "=r"(r2), "=r"(r3) : "r"(a));
}
__device__ __forceinline__ void mma16816(float* c, const uint32_t* a, const uint32_t* b) {
    asm volatile("mma.sync.aligned.m16n8k16.row.col.f32.f16.f16.f32 "
                 "{%0,%1,%2,%3},{%4,%5,%6,%7},{%8,%9},{%0,%1,%2,%3};"
                 : "+f"(c[0]), "+f"(c[1]), "+f"(c[2]), "+f"(c[3])
                 : "r"(a[0]), "r"(a[1]), "r"(a[2]), "r"(a[3]), "r"(b[0]), "r"(b[1]));
}
__device__ __forceinline__ void cp16(uint32_t dst, const void* src, int sz) {
    asm volatile("cp.async.cg.shared.global [%0], [%1], 16, %2;\n"
                 :: "r"(dst), "l"(src), "r"(sz));
}
__device__ __forceinline__ float gelu_tanh(float v) {
    float v3 = v * v * v;
    return 0.5f * v * (1.f + tanhf(0.7978845608028654f * (v + 0.044715f * v3)));
}

// ---------------- FFN GEMMs (cp.async 4-stage, 128x256 tile, 8 warps) ----------------
// MODE 0: H = gelu(gather(g_xh) @ W1[e] + b1) -> g_hbuf (f16)   N=4096 K=1024
// MODE 1: ye = g_hbuf[e] @ W2[e] + b2         -> out (scatter)  N=1024 K=4096
template <int MODE>
__global__ void __launch_bounds__(256, 1) moe_ffn_kernel(const float* __restrict__ bias,
                                                         float* __restrict__ out) {
    constexpr int N  = (MODE == 0) ? D_HIDDEN : D_MODEL;
    constexpr int K  = (MODE == 0) ? D_MODEL  : D_HIDDEN;
    constexpr int NK = K / TK;

    const int e  = blockIdx.z;
    const int m0 = blockIdx.y * TM;
    const int n0 = blockIdx.x * TN;
    const int me = min(g_counts[e], CAP);
    if (m0 >= me) return;

    extern __shared__ char dsm[];
    __shared__ int   s_tok[TM];
    __shared__ float s_bias[TN];

    const int tid = threadIdx.x;
    if (tid < TM) {
        int slot = m0 + tid;
        s_tok[tid] = (slot < me) ? g_list[e * CAP + slot] : -1;
    }
    s_bias[tid] = bias[e * N + n0 + tid];          // 256 threads == TN
    __syncthreads();

    const __half* Bsrc = ((MODE == 0) ? g_w1h : g_w2h) + (size_t)e * D_MODEL * D_HIDDEN;

    // ---- load geometry ----
    // A tile: 128 rows x 32 halves (64B); thread t -> row t>>1, chunks c0={0,2}[t&1]
    const int arow = tid >> 1;
    const int ac0  = (tid & 1) * 2;                 // 16B-chunk index (0 or 2)
    const uint32_t aDst = (uint32_t)arow * (SA_HALVES * 2) + (uint32_t)ac0 * 16;
    const __half* aSrc;
    int aSz;
    if (MODE == 0) {
        int tok = s_tok[arow];
        aSrc = g_xh + ((tok >= 0) ? ((size_t)tok * D_MODEL) : 0) + ac0 * 8;
        aSz  = (tok >= 0) ? 16 : 0;
    } else {
        aSrc = g_hbuf + ((size_t)e * CAP + m0 + arow) * D_HIDDEN + ac0 * 8;
        aSz  = 16;
    }
    // B tile: 32 rows x 256 halves (512B); thread t, q=0..3 -> row (t>>5)+8q, chunk t&31
    const int brow = tid >> 5, bch = tid & 31;
    const __half* bSrc = Bsrc + (size_t)brow * N + n0 + bch * 8;
    const uint32_t bDst = (uint32_t)brow * (SB_HALVES * 2) + (uint32_t)bch * 16;

    uint32_t smemBase = (uint32_t)__cvta_generic_to_shared(dsm);

    auto load_stage = [&](int kt) {
        int s = kt & (NSTG - 1);
        uint32_t aS = smemBase + (uint32_t)s * STG_BYTES;
        uint32_t bS = aS + SA_BYTES;
        int ko = kt * TK;
        cp16(aS + aDst,      aSrc + ko,      aSz);
        cp16(aS + aDst + 16, aSrc + ko + 8,  aSz);
#pragma unroll
        for (int q = 0; q < 4; ++q)
            cp16(bS + bDst + (uint32_t)q * 8 * (SB_HALVES * 2),
                 bSrc + (size_t)(ko + q * 8) * N, 16);
        asm volatile("cp.async.commit_group;\n");
    };

#pragma unroll
    for (int kt = 0; kt < NSTG - 1; ++kt) load_stage(kt);

    // ---- compute geometry ----
    const int wid = tid >> 5, lane = tid & 31;
    const int wr = wid & 1, wc = wid >> 1;              // warp tile 64 x 64
    const int lrow = lane & 15, lkh = (lane >> 4) << 3;

    float acc[4][8][4];
#pragma unroll
    for (int mi = 0; mi < 4; ++mi)
#pragma unroll
        for (int nj = 0; nj < 8; ++nj)
#pragma unroll
            for (int q = 0; q < 4; ++q) acc[mi][nj][q] = 0.f;

#pragma unroll 1
    for (int kt = 0; kt < NK; ++kt) {
        asm volatile("cp.async.wait_group 2;\n");
        __syncthreads();

        {   // keep pipeline full (redundant tail load keeps commit groups balanced)
            int ktn = kt + NSTG - 1;
            if (ktn >= NK) ktn = NK - 1;
            load_stage(ktn);
        }

        const int s = kt & (NSTG - 1);
        const __half* sA = (const __half*)(dsm + (size_t)s * STG_BYTES);
        const __half* sB = (const __half*)(dsm + (size_t)s * STG_BYTES + SA_BYTES);

#pragma unroll
        for (int kk = 0; kk < 2; ++kk) {
            const int ks = kk * 16;
            uint32_t af[4][4];
#pragma unroll
            for (int mi = 0; mi < 4; ++mi)
                ldsm4(af[mi][0], af[mi][1], af[mi][2], af[mi][3],
                      sA + (wr * 64 + mi * 16 + lrow) * SA_HALVES + ks + lkh);
            uint32_t bf[8][2];
#pragma unroll
            for (int nq = 0; nq < 4; ++nq) {
                uint32_t r0, r1, r2, r3;
                ldsm4t(r0, r1, r2, r3,
                       sB + (ks + lrow) * SB_HALVES + wc * 64 + nq * 16 + lkh);
                bf[nq * 2][0] = r0; bf[nq * 2][1] = r1;
                bf[nq * 2 + 1][0] = r2; bf[nq * 2 + 1][1] = r3;
            }
#pragma unroll
            for (int mi = 0; mi < 4; ++mi)
#pragma unroll
                for (int nj = 0; nj < 8; ++nj)
                    mma16816(acc[mi][nj], af[mi], bf[nj]);
        }
        __syncthreads();
    }
    asm volatile("cp.async.wait_group 0;\n");

    // ---- epilogue ----
#pragma unroll
    for (int mi = 0; mi < 4; ++mi) {
        const int r0 = wr * 64 + mi * 16 + (lane >> 2);
#pragma unroll
        for (int nj = 0; nj < 8; ++nj) {
            const int cl = wc * 64 + nj * 8 + (lane & 3) * 2;   // local col in [0,256)
            if (MODE == 0) {
                float bb0 = s_bias[cl], bb1 = s_bias[cl + 1];
                __half* hb = g_hbuf + ((size_t)e * CAP + m0) * D_HIDDEN + n0 + cl;
                float v0 = gelu_tanh(acc[mi][nj][0] + bb0);
                float v1 = gelu_tanh(acc[mi][nj][1] + bb1);
                float v2 = gelu_tanh(acc[mi][nj][2] + bb0);
                float v3 = gelu_tanh(acc[mi][nj][3] + bb1);
                *(__half2*)(hb + (size_t)r0 * D_HIDDEN)       = __floats2half2_rn(v0, v1);
                *(__half2*)(hb + (size_t)(r0 + 8) * D_HIDDEN) = __floats2half2_rn(v2, v3);
            } else {
                float bb0 = s_bias[cl], bb1 = s_bias[cl + 1];
                int tok0 = s_tok[r0], tok1 = s_tok[r0 + 8];
                if (tok0 >= 0) {
                    float2 v; v.x = acc[mi][nj][0] + bb0; v.y = acc[mi][nj][1] + bb1;
                    *(float2*)(out + (size_t)tok0 * D_MODEL + n0 + cl) = v;
                }
                if (tok1 >= 0) {
                    float2 v; v.x = acc[mi][nj][2] + bb0; v.y = acc[mi][nj][3] + bb1;
                    *(float2*)(out + (size_t)tok1 * D_MODEL + n0 + cl) = v;
                }
            }
        }
    }
}

// ---------------- launch ----------------
extern "C" void kernel_launch(void* const* d_in, const int* in_sizes, int n_in,
                              void* d_out, int out_size) {
    const float* x  = (const float*)d_in[0];
    const float* gw = (const float*)d_in[1];
    const float* w1 = (const float*)d_in[2];
    const float* b1 = (const float*)d_in[3];
    const float* w2 = (const float*)d_in[4];
    const float* b2 = (const float*)d_in[5];
    float*       out = (float*)d_out;

    zero_counts_kernel<<<1, 32>>>();
    cvt_w1_kernel<<<2048, 256>>>((const float4*)w1);
    cvt_w2_kernel<<<2048, 256>>>((const float4*)w2);

    cudaFuncSetAttribute(gating_kernel, cudaFuncAttributeMaxDynamicSharedMemorySize, 65536);
    gating_kernel<<<BTOK / 8, 256, 65536>>>((const float4*)x, (const float4*)gw);

    build_list_kernel<<<BTOK / 256, 256>>>();
    stats_kernel<<<1, 32>>>(out, (long long)out_size);

    // default: y = x (routed rows overwritten by GEMM2 epilogue)
    cudaMemcpyAsync(d_out, (const void*)x, (size_t)BTOK * D_MODEL * sizeof(float),
                    cudaMemcpyDeviceToDevice);

    cudaFuncSetAttribute(moe_ffn_kernel<0>, cudaFuncAttributeMaxDynamicSharedMemorySize, SMEM_TOTAL);
    cudaFuncSetAttribute(moe_ffn_kernel<1>, cudaFuncAttributeMaxDynamicSharedMemorySize, SMEM_TOTAL);
    moe_ffn_kernel<0><<<dim3(D_HIDDEN / TN, CAP / TM, NE), 256, SMEM_TOTAL>>>(b1, out);
    moe_ffn_kernel<1><<<dim3(D_MODEL / TN, CAP / TM, NE), 256, SMEM_TOTAL>>>(b2, out);
}

// round 8
// speedup vs baseline: 1.0389x; 1.0066x over previous
#include <cuda_runtime.h>
#include <cuda_fp16.h>
#include <stdint.h>

#define D_MODEL  1024
#define D_HIDDEN 4096
#define NE       16
#define BTOK     32768
#define CAP      2560

// GEMM tiling
#define TM   128
#define TN   256
#define TK   32
#define NSTG 4
#define SA_HALVES 40            // padded row stride for A tile (128 x 32)
#define SB_HALVES 264           // padded row stride for B tile (32 x 256)
#define SA_BYTES  (128 * SA_HALVES * 2)   // 10240
#define SB_BYTES  (TK * SB_HALVES * 2)    // 16896
#define STG_BYTES (SA_BYTES + SB_BYTES)   // 27136
#define SMEM_TOTAL (NSTG * STG_BYTES)     // 108544

static __device__ __align__(256) __half g_xh  [(size_t)BTOK * D_MODEL];
static __device__ __align__(256) __half g_w1h [(size_t)NE * D_MODEL * D_HIDDEN];
static __device__ __align__(256) __half g_w2h [(size_t)NE * D_HIDDEN * D_MODEL];
static __device__ __align__(256) __half g_hbuf[(size_t)NE * CAP * D_HIDDEN];
static __device__ int g_eid[BTOK];
static __device__ int g_keep[BTOK];
static __device__ int g_counts[NE];
static __device__ int g_fill[NE];
static __device__ int g_list[NE * CAP];

// ---------------- small kernels ----------------
__global__ void zero_counts_kernel() {
    if (threadIdx.x < NE) { g_counts[threadIdx.x] = 0; g_fill[threadIdx.x] = 0; }
}

__global__ void cvt_w1_kernel(const float4* __restrict__ src) {
    __half2* dst = (__half2*)g_w1h;
    const int n4 = NE * D_MODEL * (D_HIDDEN / 4);
    for (int i = blockIdx.x * blockDim.x + threadIdx.x; i < n4; i += gridDim.x * blockDim.x) {
        float4 v = src[i];
        dst[2 * i + 0] = __floats2half2_rn(v.x, v.y);
        dst[2 * i + 1] = __floats2half2_rn(v.z, v.w);
    }
}
__global__ void cvt_w2_kernel(const float4* __restrict__ src) {
    __half2* dst = (__half2*)g_w2h;
    const int n4 = NE * D_MODEL * (D_HIDDEN / 4);
    for (int i = blockIdx.x * blockDim.x + threadIdx.x; i < n4; i += gridDim.x * blockDim.x) {
        float4 v = src[i];
        dst[2 * i + 0] = __floats2half2_rn(v.x, v.y);
        dst[2 * i + 1] = __floats2half2_rn(v.z, v.w);
    }
}

// one warp per TWO tokens; fp32 logits (argmax must match reference);
// per-expert accumulation order identical to previous passing version.
__global__ void gating_kernel(const float4* __restrict__ x4, const float4* __restrict__ gw4) {
    extern __shared__ float4 sgw[];   // 16 x 256 float4 = 64 KB
    for (int i = threadIdx.x; i < NE * (D_MODEL / 4); i += blockDim.x) sgw[i] = gw4[i];
    __syncthreads();

    const int warp = threadIdx.x >> 5, lane = threadIdx.x & 31;
    const int t0 = blockIdx.x * 16 + warp * 2;
    const int t1 = t0 + 1;
    const float4* xr0 = x4 + (size_t)t0 * (D_MODEL / 4);
    const float4* xr1 = x4 + (size_t)t1 * (D_MODEL / 4);
    __half2* xo0 = (__half2*)g_xh + (size_t)t0 * (D_MODEL / 2);
    __half2* xo1 = (__half2*)g_xh + (size_t)t1 * (D_MODEL / 2);

    float a0[NE], a1[NE];
#pragma unroll
    for (int e = 0; e < NE; ++e) { a0[e] = 0.f; a1[e] = 0.f; }
#pragma unroll
    for (int i = 0; i < 8; ++i) {
        int d = i * 32 + lane;
        float4 v0 = xr0[d];
        float4 v1 = xr1[d];
        xo0[d * 2 + 0] = __floats2half2_rn(v0.x, v0.y);
        xo0[d * 2 + 1] = __floats2half2_rn(v0.z, v0.w);
        xo1[d * 2 + 0] = __floats2half2_rn(v1.x, v1.y);
        xo1[d * 2 + 1] = __floats2half2_rn(v1.z, v1.w);
#pragma unroll
        for (int e = 0; e < NE; ++e) {
            float4 g = sgw[e * (D_MODEL / 4) + d];
            a0[e] += v0.x * g.x + v0.y * g.y + v0.z * g.z + v0.w * g.w;
            a1[e] += v1.x * g.x + v1.y * g.y + v1.z * g.z + v1.w * g.w;
        }
    }
#pragma unroll
    for (int e = 0; e < NE; ++e)
#pragma unroll
        for (int o = 16; o > 0; o >>= 1) {
            a0[e] += __shfl_xor_sync(0xffffffffu, a0[e], o);
            a1[e] += __shfl_xor_sync(0xffffffffu, a1[e], o);
        }

    if (lane == 0) {
        float mx = a0[0]; int am = 0;
#pragma unroll
        for (int e = 1; e < NE; ++e) if (a0[e] > mx) { mx = a0[e]; am = e; }
        g_eid[t0] = am;
        atomicAdd(&g_counts[am], 1);
        float mx1 = a1[0]; int am1 = 0;
#pragma unroll
        for (int e = 1; e < NE; ++e) if (a1[e] > mx1) { mx1 = a1[e]; am1 = e; }
        g_eid[t1] = am1;
        atomicAdd(&g_counts[am1], 1);
    }
}

__global__ void build_list_kernel() {
    int t = blockIdx.x * blockDim.x + threadIdx.x;
    if (t >= BTOK) return;
    int e = g_eid[t];
    int p = atomicAdd(&g_fill[e], 1);
    if (p < CAP) { g_list[e * CAP + p] = t; g_keep[t] = 1; }
    else         { g_keep[t] = 0; }
}

// copy x rows only for dropped tokens (none in the typical balanced case)
__global__ void copy_dropped_kernel(const float4* __restrict__ x4, float4* __restrict__ out4) {
    const int warp = threadIdx.x >> 5, lane = threadIdx.x & 31;
    const int t = blockIdx.x * 8 + warp;
    if (g_keep[t]) return;
    const float4* src = x4 + (size_t)t * (D_MODEL / 4);
    float4* dst = out4 + (size_t)t * (D_MODEL / 4);
#pragma unroll
    for (int i = 0; i < 8; ++i) dst[i * 32 + lane] = src[i * 32 + lane];
}

__global__ void stats_kernel(float* __restrict__ out, long long out_size) {
    int e = threadIdx.x;
    float c  = (e < NE) ? (float)g_counts[e] : 0.f;
    const float expc = (float)BTOK / NE;
    float d  = (e < NE) ? (c - expc) * (c - expc) : 0.f;
    float ov = (e < NE) ? fmaxf(c - (float)CAP, 0.f) : 0.f;
#pragma unroll
    for (int o = 16; o > 0; o >>= 1) {
        d  += __shfl_xor_sync(0xffffffffu, d,  o);
        ov += __shfl_xor_sync(0xffffffffu, ov, o);
    }
    if (threadIdx.x == 0) {
        float lb = (d / NE) / (expc * expc);
        if (out_size > (long long)BTOK * D_MODEL)     out[(long long)BTOK * D_MODEL]     = lb;
        if (out_size > (long long)BTOK * D_MODEL + 1) out[(long long)BTOK * D_MODEL + 1] = ov / (float)BTOK;
    }
}

// ---------------- mma helpers ----------------
__device__ __forceinline__ void ldsm4(uint32_t& r0, uint32_t& r1, uint32_t& r2, uint32_t& r3,
                                      const void* p) {
    uint32_t a = (uint32_t)__cvta_generic_to_shared(p);
    asm volatile("ldmatrix.sync.aligned.m8n8.x4.shared.b16 {%0,%1,%2,%3},[%4];"
                 : "=r"(r0), "=r"(r1), "=r"(r2), "=r"(r3) : "r"(a));
}
__device__ __forceinline__ void ldsm4t(uint32_t& r0, uint32_t& r1, uint32_t& r2, uint32_t& r3,
                                       const void* p) {
    uint32_t a = (uint32_t)__cvta_generic_to_shared(p);
    asm volatile("ldmatrix.sync.aligned.m8n8.x4.trans.shared.b16 {%0,%1,%2,%3},[%4];"
                 : "=r"(r0), "=r"(r1), "=r"(r2), "=r"(r3) : "r"(a));
}
__device__ __forceinline__ void mma16816(float* c, const uint32_t* a, const uint32_t* b) {
    asm volatile("mma.sync.aligned.m16n8k16.row.col.f32.f16.f16.f32 "
                 "{%0,%1,%2,%3},{%4,%5,%6,%7},{%8,%9},{%0,%1,%2,%3};"
                 : "+f"(c[0]), "+f"(c[1]), "+f"(c[2]), "+f"(c[3])
                 : "r"(a[0]), "r"(a[1]), "r"(a[2]), "r"(a[3]), "r"(b[0]), "r"(b[1]));
}
__device__ __forceinline__ void cp16(uint32_t dst, const void* src, int sz) {
    asm volatile("cp.async.cg.shared.global [%0], [%1], 16, %2;\n"
                 :: "r"(dst), "l"(src), "r"(sz));
}
__device__ __forceinline__ float gelu_tanh(float v) {
    float v3 = v * v * v;
    return 0.5f * v * (1.f + tanhf(0.7978845608028654f * (v + 0.044715f * v3)));
}

// ---------------- FFN GEMMs (cp.async 4-stage, 128x256 tile, 8 warps) ----------------
// single __syncthreads per K-tile; batched fragment loads (both kk halves)
// MODE 0: H = gelu(gather(g_xh) @ W1[e] + b1) -> g_hbuf (f16)   N=4096 K=1024
// MODE 1: ye = g_hbuf[e] @ W2[e] + b2         -> out (scatter)  N=1024 K=4096
template <int MODE>
__global__ void __launch_bounds__(256, 1) moe_ffn_kernel(const float* __restrict__ bias,
                                                         float* __restrict__ out) {
    constexpr int N  = (MODE == 0) ? D_HIDDEN : D_MODEL;
    constexpr int K  = (MODE == 0) ? D_MODEL  : D_HIDDEN;
    constexpr int NK = K / TK;

    const int e  = blockIdx.z;
    const int m0 = blockIdx.y * TM;
    const int n0 = blockIdx.x * TN;
    const int me = min(g_counts[e], CAP);
    if (m0 >= me) return;

    extern __shared__ char dsm[];
    __shared__ int   s_tok[TM];
    __shared__ float s_bias[TN];

    const int tid = threadIdx.x;
    if (tid < TM) {
        int slot = m0 + tid;
        s_tok[tid] = (slot < me) ? g_list[e * CAP + slot] : -1;
    }
    s_bias[tid] = bias[e * N + n0 + tid];          // 256 threads == TN
    __syncthreads();

    const __half* Bsrc = ((MODE == 0) ? g_w1h : g_w2h) + (size_t)e * D_MODEL * D_HIDDEN;

    // ---- load geometry ----
    const int arow = tid >> 1;
    const int ac0  = (tid & 1) * 2;                 // 16B-chunk index (0 or 2)
    const uint32_t aDst = (uint32_t)arow * (SA_HALVES * 2) + (uint32_t)ac0 * 16;
    const __half* aSrc;
    int aSz;
    if (MODE == 0) {
        int tok = s_tok[arow];
        aSrc = g_xh + ((tok >= 0) ? ((size_t)tok * D_MODEL) : 0) + ac0 * 8;
        aSz  = (tok >= 0) ? 16 : 0;
    } else {
        aSrc = g_hbuf + ((size_t)e * CAP + m0 + arow) * D_HIDDEN + ac0 * 8;
        aSz  = 16;
    }
    const int brow = tid >> 5, bch = tid & 31;
    const __half* bSrc = Bsrc + (size_t)brow * N + n0 + bch * 8;
    const uint32_t bDst = (uint32_t)brow * (SB_HALVES * 2) + (uint32_t)bch * 16;

    uint32_t smemBase = (uint32_t)__cvta_generic_to_shared(dsm);

    auto load_stage = [&](int kt) {
        int s = kt & (NSTG - 1);
        uint32_t aS = smemBase + (uint32_t)s * STG_BYTES;
        uint32_t bS = aS + SA_BYTES;
        int ko = kt * TK;
        cp16(aS + aDst,      aSrc + ko,      aSz);
        cp16(aS + aDst + 16, aSrc + ko + 8,  aSz);
#pragma unroll
        for (int q = 0; q < 4; ++q)
            cp16(bS + bDst + (uint32_t)q * 8 * (SB_HALVES * 2),
                 bSrc + (size_t)(ko + q * 8) * N, 16);
        asm volatile("cp.async.commit_group;\n");
    };

#pragma unroll
    for (int kt = 0; kt < NSTG - 1; ++kt) load_stage(kt);

    // ---- compute geometry ----
    const int wid = tid >> 5, lane = tid & 31;
    const int wr = wid & 1, wc = wid >> 1;              // warp tile 64 x 64
    const int lrow = lane & 15, lkh = (lane >> 4) << 3;

    float acc[4][8][4];
#pragma unroll
    for (int mi = 0; mi < 4; ++mi)
#pragma unroll
        for (int nj = 0; nj < 8; ++nj)
#pragma unroll
            for (int q = 0; q < 4; ++q) acc[mi][nj][q] = 0.f;

#pragma unroll 1
    for (int kt = 0; kt < NK; ++kt) {
        asm volatile("cp.async.wait_group %0;\n" :: "n"(NSTG - 2));
        __syncthreads();   // single barrier: protects stage (kt-1) overwrite below

        // start next global prefetch ASAP (writes stage (kt-1)&3, all warps done with it)
        int ktn = kt + NSTG - 1;
        if (ktn < NK) load_stage(ktn);

        const int s = kt & (NSTG - 1);
        const __half* sA = (const __half*)(dsm + (size_t)s * STG_BYTES);
        const __half* sB = (const __half*)(dsm + (size_t)s * STG_BYTES + SA_BYTES);

        // batch ALL fragment loads for both kk halves, then run all mmas
        uint32_t af[2][4][4];
        uint32_t bf[2][8][2];
#pragma unroll
        for (int kk = 0; kk < 2; ++kk) {
            const int ks = kk * 16;
#pragma unroll
            for (int mi = 0; mi < 4; ++mi)
                ldsm4(af[kk][mi][0], af[kk][mi][1], af[kk][mi][2], af[kk][mi][3],
                      sA + (wr * 64 + mi * 16 + lrow) * SA_HALVES + ks + lkh);
#pragma unroll
            for (int nq = 0; nq < 4; ++nq) {
                uint32_t r0, r1, r2, r3;
                ldsm4t(r0, r1, r2, r3,
                       sB + (ks + lrow) * SB_HALVES + wc * 64 + nq * 16 + lkh);
                bf[kk][nq * 2][0] = r0; bf[kk][nq * 2][1] = r1;
                bf[kk][nq * 2 + 1][0] = r2; bf[kk][nq * 2 + 1][1] = r3;
            }
        }
#pragma unroll
        for (int kk = 0; kk < 2; ++kk)
#pragma unroll
            for (int mi = 0; mi < 4; ++mi)
#pragma unroll
                for (int nj = 0; nj < 8; ++nj)
                    mma16816(acc[mi][nj], af[kk][mi], bf[kk][nj]);
    }
    asm volatile("cp.async.wait_group 0;\n");

    // ---- epilogue ----
#pragma unroll
    for (int mi = 0; mi < 4; ++mi) {
        const int r0 = wr * 64 + mi * 16 + (lane >> 2);
#pragma unroll
        for (int nj = 0; nj < 8; ++nj) {
            const int cl = wc * 64 + nj * 8 + (lane & 3) * 2;   // local col in [0,256)
            if (MODE == 0) {
                float bb0 = s_bias[cl], bb1 = s_bias[cl + 1];
                __half* hb = g_hbuf + ((size_t)e * CAP + m0) * D_HIDDEN + n0 + cl;
                float v0 = gelu_tanh(acc[mi][nj][0] + bb0);
                float v1 = gelu_tanh(acc[mi][nj][1] + bb1);
                float v2 = gelu_tanh(acc[mi][nj][2] + bb0);
                float v3 = gelu_tanh(acc[mi][nj][3] + bb1);
                *(__half2*)(hb + (size_t)r0 * D_HIDDEN)       = __floats2half2_rn(v0, v1);
                *(__half2*)(hb + (size_t)(r0 + 8) * D_HIDDEN) = __floats2half2_rn(v2, v3);
            } else {
                float bb0 = s_bias[cl], bb1 = s_bias[cl + 1];
                int tok0 = s_tok[r0], tok1 = s_tok[r0 + 8];
                if (tok0 >= 0) {
                    float2 v; v.x = acc[mi][nj][0] + bb0; v.y = acc[mi][nj][1] + bb1;
                    *(float2*)(out + (size_t)tok0 * D_MODEL + n0 + cl) = v;
                }
                if (tok1 >= 0) {
                    float2 v; v.x = acc[mi][nj][2] + bb0; v.y = acc[mi][nj][3] + bb1;
                    *(float2*)(out + (size_t)tok1 * D_MODEL + n0 + cl) = v;
                }
            }
        }
    }
}

// ---------------- launch ----------------
extern "C" void kernel_launch(void* const* d_in, const int* in_sizes, int n_in,
                              void* d_out, int out_size) {
    const float* x  = (const float*)d_in[0];
    const float* gw = (const float*)d_in[1];
    const float* w1 = (const float*)d_in[2];
    const float* b1 = (const float*)d_in[3];
    const float* w2 = (const float*)d_in[4];
    const float* b2 = (const float*)d_in[5];
    float*       out = (float*)d_out;

    zero_counts_kernel<<<1, 32>>>();
    cvt_w1_kernel<<<2048, 256>>>((const float4*)w1);
    cvt_w2_kernel<<<2048, 256>>>((const float4*)w2);

    cudaFuncSetAttribute(gating_kernel, cudaFuncAttributeMaxDynamicSharedMemorySize, 65536);
    gating_kernel<<<BTOK / 16, 256, 65536>>>((const float4*)x, (const float4*)gw);

    build_list_kernel<<<BTOK / 256, 256>>>();
    stats_kernel<<<1, 32>>>(out, (long long)out_size);

    // only dropped tokens need y = x (kept rows fully overwritten by GEMM2 epilogue)
    copy_dropped_kernel<<<BTOK / 8, 256>>>((const float4*)x, (float4*)out);

    cudaFuncSetAttribute(moe_ffn_kernel<0>, cudaFuncAttributeMaxDynamicSharedMemorySize, SMEM_TOTAL);
    cudaFuncSetAttribute(moe_ffn_kernel<1>, cudaFuncAttributeMaxDynamicSharedMemorySize, SMEM_TOTAL);
    moe_ffn_kernel<0><<<dim3(D_HIDDEN / TN, CAP / TM, NE), 256, SMEM_TOTAL>>>(b1, out);
    moe_ffn_kernel<1><<<dim3(D_MODEL / TN, CAP / TM, NE), 256, SMEM_TOTAL>>>(b2, out);
}

// round 9
// speedup vs baseline: 1.0598x; 1.0201x over previous
#include <cuda_runtime.h>
#include <cuda_fp16.h>
#include <stdint.h>

#define D_MODEL  1024
#define D_HIDDEN 4096
#define NE       16
#define BTOK     32768
#define CAP      2560

// GEMM tiling
#define TM   128
#define TN   256
#define TK   32
#define NSTG 4
#define SA_HALVES 40            // padded row stride for A tile (128 x 32)
#define SB_HALVES 264           // padded row stride for B tile (32 x 256)
#define SA_BYTES  (128 * SA_HALVES * 2)   // 10240
#define SB_BYTES  (TK * SB_HALVES * 2)    // 16896
#define STG_BYTES (SA_BYTES + SB_BYTES)   // 27136
#define SMEM_TOTAL (NSTG * STG_BYTES)     // 108544

static __device__ __align__(256) __half g_xh  [(size_t)BTOK * D_MODEL];
static __device__ __align__(256) __half g_w1h [(size_t)NE * D_MODEL * D_HIDDEN];
static __device__ __align__(256) __half g_w2h [(size_t)NE * D_HIDDEN * D_MODEL];
static __device__ __align__(256) __half g_hbuf[(size_t)NE * CAP * D_HIDDEN];
static __device__ int g_eid[BTOK];
static __device__ int g_keep[BTOK];
static __device__ int g_counts[NE];
static __device__ int g_fill[NE];
static __device__ int g_list[NE * CAP];

// ---------------- small kernels ----------------
__global__ void zero_counts_kernel() {
    if (threadIdx.x < NE) { g_counts[threadIdx.x] = 0; g_fill[threadIdx.x] = 0; }
}

__global__ void cvt_w1_kernel(const float4* __restrict__ src) {
    __half2* dst = (__half2*)g_w1h;
    const int n4 = NE * D_MODEL * (D_HIDDEN / 4);
    for (int i = blockIdx.x * blockDim.x + threadIdx.x; i < n4; i += gridDim.x * blockDim.x) {
        float4 v = src[i];
        dst[2 * i + 0] = __floats2half2_rn(v.x, v.y);
        dst[2 * i + 1] = __floats2half2_rn(v.z, v.w);
    }
}
__global__ void cvt_w2_kernel(const float4* __restrict__ src) {
    __half2* dst = (__half2*)g_w2h;
    const int n4 = NE * D_MODEL * (D_HIDDEN / 4);
    for (int i = blockIdx.x * blockDim.x + threadIdx.x; i < n4; i += gridDim.x * blockDim.x) {
        float4 v = src[i];
        dst[2 * i + 0] = __floats2half2_rn(v.x, v.y);
        dst[2 * i + 1] = __floats2half2_rn(v.z, v.w);
    }
}

// one warp per TWO tokens; fp32 logits (argmax must match reference).
__global__ void gating_kernel(const float4* __restrict__ x4, const float4* __restrict__ gw4) {
    extern __shared__ float4 sgw[];   // 16 x 256 float4 = 64 KB
    for (int i = threadIdx.x; i < NE * (D_MODEL / 4); i += blockDim.x) sgw[i] = gw4[i];
    __syncthreads();

    const int warp = threadIdx.x >> 5, lane = threadIdx.x & 31;
    const int t0 = blockIdx.x * 16 + warp * 2;
    const int t1 = t0 + 1;
    const float4* xr0 = x4 + (size_t)t0 * (D_MODEL / 4);
    const float4* xr1 = x4 + (size_t)t1 * (D_MODEL / 4);
    __half2* xo0 = (__half2*)g_xh + (size_t)t0 * (D_MODEL / 2);
    __half2* xo1 = (__half2*)g_xh + (size_t)t1 * (D_MODEL / 2);

    float a0[NE], a1[NE];
#pragma unroll
    for (int e = 0; e < NE; ++e) { a0[e] = 0.f; a1[e] = 0.f; }
#pragma unroll
    for (int i = 0; i < 8; ++i) {
        int d = i * 32 + lane;
        float4 v0 = xr0[d];
        float4 v1 = xr1[d];
        xo0[d * 2 + 0] = __floats2half2_rn(v0.x, v0.y);
        xo0[d * 2 + 1] = __floats2half2_rn(v0.z, v0.w);
        xo1[d * 2 + 0] = __floats2half2_rn(v1.x, v1.y);
        xo1[d * 2 + 1] = __floats2half2_rn(v1.z, v1.w);
#pragma unroll
        for (int e = 0; e < NE; ++e) {
            float4 g = sgw[e * (D_MODEL / 4) + d];
            a0[e] += v0.x * g.x + v0.y * g.y + v0.z * g.z + v0.w * g.w;
            a1[e] += v1.x * g.x + v1.y * g.y + v1.z * g.z + v1.w * g.w;
        }
    }
#pragma unroll
    for (int e = 0; e < NE; ++e)
#pragma unroll
        for (int o = 16; o > 0; o >>= 1) {
            a0[e] += __shfl_xor_sync(0xffffffffu, a0[e], o);
            a1[e] += __shfl_xor_sync(0xffffffffu, a1[e], o);
        }

    if (lane == 0) {
        float mx = a0[0]; int am = 0;
#pragma unroll
        for (int e = 1; e < NE; ++e) if (a0[e] > mx) { mx = a0[e]; am = e; }
        g_eid[t0] = am;
        atomicAdd(&g_counts[am], 1);
        float mx1 = a1[0]; int am1 = 0;
#pragma unroll
        for (int e = 1; e < NE; ++e) if (a1[e] > mx1) { mx1 = a1[e]; am1 = e; }
        g_eid[t1] = am1;
        atomicAdd(&g_counts[am1], 1);
    }
}

__global__ void build_list_kernel() {
    int t = blockIdx.x * blockDim.x + threadIdx.x;
    if (t >= BTOK) return;
    int e = g_eid[t];
    int p = atomicAdd(&g_fill[e], 1);
    if (p < CAP) { g_list[e * CAP + p] = t; g_keep[t] = 1; }
    else         { g_keep[t] = 0; }
}

// copy x rows only for dropped tokens (none in the typical balanced case)
__global__ void copy_dropped_kernel(const float4* __restrict__ x4, float4* __restrict__ out4) {
    const int warp = threadIdx.x >> 5, lane = threadIdx.x & 31;
    const int t = blockIdx.x * 8 + warp;
    if (g_keep[t]) return;
    const float4* src = x4 + (size_t)t * (D_MODEL / 4);
    float4* dst = out4 + (size_t)t * (D_MODEL / 4);
#pragma unroll
    for (int i = 0; i < 8; ++i) dst[i * 32 + lane] = src[i * 32 + lane];
}

__global__ void stats_kernel(float* __restrict__ out, long long out_size) {
    int e = threadIdx.x;
    float c  = (e < NE) ? (float)g_counts[e] : 0.f;
    const float expc = (float)BTOK / NE;
    float d  = (e < NE) ? (c - expc) * (c - expc) : 0.f;
    float ov = (e < NE) ? fmaxf(c - (float)CAP, 0.f) : 0.f;
#pragma unroll
    for (int o = 16; o > 0; o >>= 1) {
        d  += __shfl_xor_sync(0xffffffffu, d,  o);
        ov += __shfl_xor_sync(0xffffffffu, ov, o);
    }
    if (threadIdx.x == 0) {
        float lb = (d / NE) / (expc * expc);
        if (out_size > (long long)BTOK * D_MODEL)     out[(long long)BTOK * D_MODEL]     = lb;
        if (out_size > (long long)BTOK * D_MODEL + 1) out[(long long)BTOK * D_MODEL + 1] = ov / (float)BTOK;
    }
}

// ---------------- mma helpers ----------------
__device__ __forceinline__ void ldsm4(uint32_t& r0, uint32_t& r1, uint32_t& r2, uint32_t& r3,
                                      const void* p) {
    uint32_t a = (uint32_t)__cvta_generic_to_shared(p);
    asm volatile("ldmatrix.sync.aligned.m8n8.x4.shared.b16 {%0,%1,%2,%3},[%4];"
                 : "=r"(r0), "=r"(r1), "=r"(r2), "=r"(r3) : "r"(a));
}
__device__ __forceinline__ void ldsm4t(uint32_t& r0, uint32_t& r1, uint32_t& r2, uint32_t& r3,
                                       const void* p) {
    uint32_t a = (uint32_t)__cvta_generic_to_shared(p);
    asm volatile("ldmatrix.sync.aligned.m8n8.x4.trans.shared.b16 {%0,%1,%2,%3},[%4];"
                 : "=r"(r0), "=r"(r1), "=r"(r2), "=r"(r3) : "r"(a));
}
__device__ __forceinline__ void mma16816(float* c, const uint32_t* a, const uint32_t* b) {
    asm volatile("mma.sync.aligned.m16n8k16.row.col.f32.f16.f16.f32 "
                 "{%0,%1,%2,%3},{%4,%5,%6,%7},{%8,%9},{%0,%1,%2,%3};"
                 : "+f"(c[0]), "+f"(c[1]), "+f"(c[2]), "+f"(c[3])
                 : "r"(a[0]), "r"(a[1]), "r"(a[2]), "r"(a[3]), "r"(b[0]), "r"(b[1]));
}
__device__ __forceinline__ void cp16(uint32_t dst, const void* src, int sz) {
    asm volatile("cp.async.cg.shared.global [%0], [%1], 16, %2;\n"
                 :: "r"(dst), "l"(src), "r"(sz));
}
__device__ __forceinline__ float gelu_tanh(float v) {
    float v3 = v * v * v;
    return 0.5f * v * (1.f + tanhf(0.7978845608028654f * (v + 0.044715f * v3)));
}

// ---------------- FFN GEMMs (cp.async 4-stage, 128x256 tile, 16 warps) ----------------
// warp tile 64x32 -> 64-reg accumulator, 4 warps/SMSP for latency hiding
// MODE 0: H = gelu(gather(g_xh) @ W1[e] + b1) -> g_hbuf (f16)   N=4096 K=1024
// MODE 1: ye = g_hbuf[e] @ W2[e] + b2         -> out (scatter)  N=1024 K=4096
template <int MODE>
__global__ void __launch_bounds__(512, 1) moe_ffn_kernel(const float* __restrict__ bias,
                                                         float* __restrict__ out) {
    constexpr int N  = (MODE == 0) ? D_HIDDEN : D_MODEL;
    constexpr int K  = (MODE == 0) ? D_MODEL  : D_HIDDEN;
    constexpr int NK = K / TK;

    const int e  = blockIdx.z;
    const int m0 = blockIdx.y * TM;
    const int n0 = blockIdx.x * TN;
    const int me = min(g_counts[e], CAP);
    if (m0 >= me) return;

    extern __shared__ char dsm[];
    __shared__ int   s_tok[TM];
    __shared__ float s_bias[TN];

    const int tid = threadIdx.x;
    if (tid < TM) {
        int slot = m0 + tid;
        s_tok[tid] = (slot < me) ? g_list[e * CAP + slot] : -1;
    }
    if (tid < TN) s_bias[tid] = bias[e * N + n0 + tid];
    __syncthreads();

    const __half* Bsrc = ((MODE == 0) ? g_w1h : g_w2h) + (size_t)e * D_MODEL * D_HIDDEN;

    // ---- load geometry (512 threads) ----
    // A tile: 128 rows x 4 chunks(16B) = 512 -> 1 chunk/thread
    const int arow = tid >> 2;
    const int ach  = tid & 3;
    const uint32_t aDst = (uint32_t)arow * (SA_HALVES * 2) + (uint32_t)ach * 16;
    const __half* aSrc;
    int aSz;
    if (MODE == 0) {
        int tok = s_tok[arow];
        aSrc = g_xh + ((tok >= 0) ? ((size_t)tok * D_MODEL) : 0) + ach * 8;
        aSz  = (tok >= 0) ? 16 : 0;
    } else {
        aSrc = g_hbuf + ((size_t)e * CAP + m0 + arow) * D_HIDDEN + ach * 8;
        aSz  = 16;
    }
    // B tile: 32 rows x 32 chunks = 1024 -> 2 chunks/thread (rows brow, brow+16)
    const int brow = tid >> 5, bch = tid & 31;
    const __half* bSrc = Bsrc + (size_t)brow * N + n0 + bch * 8;
    const uint32_t bDst = (uint32_t)brow * (SB_HALVES * 2) + (uint32_t)bch * 16;

    uint32_t smemBase = (uint32_t)__cvta_generic_to_shared(dsm);

    auto load_stage = [&](int kt) {
        int s = kt & (NSTG - 1);
        uint32_t aS = smemBase + (uint32_t)s * STG_BYTES;
        uint32_t bS = aS + SA_BYTES;
        int ko = kt * TK;
        cp16(aS + aDst, aSrc + ko, aSz);
        cp16(bS + bDst,                                   bSrc + (size_t)ko * N, 16);
        cp16(bS + bDst + (uint32_t)16 * (SB_HALVES * 2),  bSrc + (size_t)(ko + 16) * N, 16);
        asm volatile("cp.async.commit_group;\n");
    };

#pragma unroll
    for (int kt = 0; kt < NSTG - 1; ++kt) load_stage(kt);

    // ---- compute geometry: 16 warps, warp tile 64 rows x 32 cols ----
    const int wid = tid >> 5, lane = tid & 31;
    const int wr = wid & 1, wc = wid >> 1;              // wr: 0..1, wc: 0..7
    const int lrow = lane & 15, lkh = (lane >> 4) << 3;

    float acc[4][4][4];
#pragma unroll
    for (int mi = 0; mi < 4; ++mi)
#pragma unroll
        for (int nj = 0; nj < 4; ++nj)
#pragma unroll
            for (int q = 0; q < 4; ++q) acc[mi][nj][q] = 0.f;

#pragma unroll 1
    for (int kt = 0; kt < NK; ++kt) {
        asm volatile("cp.async.wait_group %0;\n" :: "n"(NSTG - 2));
        __syncthreads();   // single barrier: protects stage (kt-1) overwrite below

        int ktn = kt + NSTG - 1;
        if (ktn < NK) load_stage(ktn);

        const int s = kt & (NSTG - 1);
        const __half* sA = (const __half*)(dsm + (size_t)s * STG_BYTES);
        const __half* sB = (const __half*)(dsm + (size_t)s * STG_BYTES + SA_BYTES);

#pragma unroll
        for (int kk = 0; kk < 2; ++kk) {
            const int ks = kk * 16;
            uint32_t af[4][4];
#pragma unroll
            for (int mi = 0; mi < 4; ++mi)
                ldsm4(af[mi][0], af[mi][1], af[mi][2], af[mi][3],
                      sA + (wr * 64 + mi * 16 + lrow) * SA_HALVES + ks + lkh);
            uint32_t bf[4][2];
#pragma unroll
            for (int nq = 0; nq < 2; ++nq) {
                uint32_t r0, r1, r2, r3;
                ldsm4t(r0, r1, r2, r3,
                       sB + (ks + lrow) * SB_HALVES + wc * 32 + nq * 16 + lkh);
                bf[nq * 2][0] = r0; bf[nq * 2][1] = r1;
                bf[nq * 2 + 1][0] = r2; bf[nq * 2 + 1][1] = r3;
            }
#pragma unroll
            for (int mi = 0; mi < 4; ++mi)
#pragma unroll
                for (int nj = 0; nj < 4; ++nj)
                    mma16816(acc[mi][nj], af[mi], bf[nj]);
        }
    }
    asm volatile("cp.async.wait_group 0;\n");

    // ---- epilogue ----
#pragma unroll
    for (int mi = 0; mi < 4; ++mi) {
        const int r0 = wr * 64 + mi * 16 + (lane >> 2);
#pragma unroll
        for (int nj = 0; nj < 4; ++nj) {
            const int cl = wc * 32 + nj * 8 + (lane & 3) * 2;   // local col in [0,256)
            if (MODE == 0) {
                float bb0 = s_bias[cl], bb1 = s_bias[cl + 1];
                __half* hb = g_hbuf + ((size_t)e * CAP + m0) * D_HIDDEN + n0 + cl;
                float v0 = gelu_tanh(acc[mi][nj][0] + bb0);
                float v1 = gelu_tanh(acc[mi][nj][1] + bb1);
                float v2 = gelu_tanh(acc[mi][nj][2] + bb0);
                float v3 = gelu_tanh(acc[mi][nj][3] + bb1);
                *(__half2*)(hb + (size_t)r0 * D_HIDDEN)       = __floats2half2_rn(v0, v1);
                *(__half2*)(hb + (size_t)(r0 + 8) * D_HIDDEN) = __floats2half2_rn(v2, v3);
            } else {
                float bb0 = s_bias[cl], bb1 = s_bias[cl + 1];
                int tok0 = s_tok[r0], tok1 = s_tok[r0 + 8];
                if (tok0 >= 0) {
                    float2 v; v.x = acc[mi][nj][0] + bb0; v.y = acc[mi][nj][1] + bb1;
                    *(float2*)(out + (size_t)tok0 * D_MODEL + n0 + cl) = v;
                }
                if (tok1 >= 0) {
                    float2 v; v.x = acc[mi][nj][2] + bb0; v.y = acc[mi][nj][3] + bb1;
                    *(float2*)(out + (size_t)tok1 * D_MODEL + n0 + cl) = v;
                }
            }
        }
    }
}

// ---------------- launch ----------------
extern "C" void kernel_launch(void* const* d_in, const int* in_sizes, int n_in,
                              void* d_out, int out_size) {
    const float* x  = (const float*)d_in[0];
    const float* gw = (const float*)d_in[1];
    const float* w1 = (const float*)d_in[2];
    const float* b1 = (const float*)d_in[3];
    const float* w2 = (const float*)d_in[4];
    const float* b2 = (const float*)d_in[5];
    float*       out = (float*)d_out;

    zero_counts_kernel<<<1, 32>>>();
    cvt_w1_kernel<<<2048, 256>>>((const float4*)w1);
    cvt_w2_kernel<<<2048, 256>>>((const float4*)w2);

    cudaFuncSetAttribute(gating_kernel, cudaFuncAttributeMaxDynamicSharedMemorySize, 65536);
    gating_kernel<<<BTOK / 16, 256, 65536>>>((const float4*)x, (const float4*)gw);

    build_list_kernel<<<BTOK / 256, 256>>>();
    stats_kernel<<<1, 32>>>(out, (long long)out_size);

    // only dropped tokens need y = x (kept rows fully overwritten by GEMM2 epilogue)
    copy_dropped_kernel<<<BTOK / 8, 256>>>((const float4*)x, (float4*)out);

    cudaFuncSetAttribute(moe_ffn_kernel<0>, cudaFuncAttributeMaxDynamicSharedMemorySize, SMEM_TOTAL);
    cudaFuncSetAttribute(moe_ffn_kernel<1>, cudaFuncAttributeMaxDynamicSharedMemorySize, SMEM_TOTAL);
    moe_ffn_kernel<0><<<dim3(D_HIDDEN / TN, CAP / TM, NE), 512, SMEM_TOTAL>>>(b1, out);
    moe_ffn_kernel<1><<<dim3(D_MODEL / TN, CAP / TM, NE), 512, SMEM_TOTAL>>>(b2, out);
}

// round 15
// speedup vs baseline: 1.1580x; 1.0927x over previous
#include <cuda_runtime.h>
#include <cuda_fp16.h>
#include <stdint.h>

#define D_MODEL  1024
#define D_HIDDEN 4096
#define NE       16
#define BTOK     32768
#define CAP      2560

// GEMM tiling (2 CTAs/SM target)
#define TM   128
#define TN   128
#define TK   32
#define NSTG 4
#define SA_HALVES 40            // padded row stride for A tile (128 x 32)
#define SB_HALVES 136           // padded row stride for B tile (32 x 128)
#define SA_BYTES  (128 * SA_HALVES * 2)   // 10240
#define SB_BYTES  (TK * SB_HALVES * 2)    // 8704
#define STG_BYTES (SA_BYTES + SB_BYTES)   // 18944
#define SMEM_TOTAL (NSTG * STG_BYTES)     // 75776

static __device__ __align__(256) __half g_xh  [(size_t)BTOK * D_MODEL];
static __device__ __align__(256) __half g_w1h [(size_t)NE * D_MODEL * D_HIDDEN];
static __device__ __align__(256) __half g_w2h [(size_t)NE * D_HIDDEN * D_MODEL];
static __device__ __align__(256) __half g_hbuf[(size_t)NE * CAP * D_HIDDEN];
static __device__ int g_eid[BTOK];
static __device__ int g_keep[BTOK];
static __device__ int g_counts[NE];
static __device__ int g_fill[NE];
static __device__ int g_list[NE * CAP];

// ---------------- small kernels ----------------
__global__ void zero_counts_kernel() {
    if (threadIdx.x < NE) { g_counts[threadIdx.x] = 0; g_fill[threadIdx.x] = 0; }
}

__global__ void cvt_w1_kernel(const float4* __restrict__ src) {
    __half2* dst = (__half2*)g_w1h;
    const int n4 = NE * D_MODEL * (D_HIDDEN / 4);
    for (int i = blockIdx.x * blockDim.x + threadIdx.x; i < n4; i += gridDim.x * blockDim.x) {
        float4 v = src[i];
        dst[2 * i + 0] = __floats2half2_rn(v.x, v.y);
        dst[2 * i + 1] = __floats2half2_rn(v.z, v.w);
    }
}
__global__ void cvt_w2_kernel(const float4* __restrict__ src) {
    __half2* dst = (__half2*)g_w2h;
    const int n4 = NE * D_MODEL * (D_HIDDEN / 4);
    for (int i = blockIdx.x * blockDim.x + threadIdx.x; i < n4; i += gridDim.x * blockDim.x) {
        float4 v = src[i];
        dst[2 * i + 0] = __floats2half2_rn(v.x, v.y);
        dst[2 * i + 1] = __floats2half2_rn(v.z, v.w);
    }
}

// one warp per TWO tokens; fp32 logits (argmax must match reference).
__global__ void gating_kernel(const float4* __restrict__ x4, const float4* __restrict__ gw4) {
    extern __shared__ float4 sgw[];   // 16 x 256 float4 = 64 KB
    for (int i = threadIdx.x; i < NE * (D_MODEL / 4); i += blockDim.x) sgw[i] = gw4[i];
    __syncthreads();

    const int warp = threadIdx.x >> 5, lane = threadIdx.x & 31;
    const int t0 = blockIdx.x * 16 + warp * 2;
    const int t1 = t0 + 1;
    const float4* xr0 = x4 + (size_t)t0 * (D_MODEL / 4);
    const float4* xr1 = x4 + (size_t)t1 * (D_MODEL / 4);
    __half2* xo0 = (__half2*)g_xh + (size_t)t0 * (D_MODEL / 2);
    __half2* xo1 = (__half2*)g_xh + (size_t)t1 * (D_MODEL / 2);

    float a0[NE], a1[NE];
#pragma unroll
    for (int e = 0; e < NE; ++e) { a0[e] = 0.f; a1[e] = 0.f; }
#pragma unroll
    for (int i = 0; i < 8; ++i) {
        int d = i * 32 + lane;
        float4 v0 = xr0[d];
        float4 v1 = xr1[d];
        xo0[d * 2 + 0] = __floats2half2_rn(v0.x, v0.y);
        xo0[d * 2 + 1] = __floats2half2_rn(v0.z, v0.w);
        xo1[d * 2 + 0] = __floats2half2_rn(v1.x, v1.y);
        xo1[d * 2 + 1] = __floats2half2_rn(v1.z, v1.w);
#pragma unroll
        for (int e = 0; e < NE; ++e) {
            float4 g = sgw[e * (D_MODEL / 4) + d];
            a0[e] += v0.x * g.x + v0.y * g.y + v0.z * g.z + v0.w * g.w;
            a1[e] += v1.x * g.x + v1.y * g.y + v1.z * g.z + v1.w * g.w;
        }
    }
#pragma unroll
    for (int e = 0; e < NE; ++e)
#pragma unroll
        for (int o = 16; o > 0; o >>= 1) {
            a0[e] += __shfl_xor_sync(0xffffffffu, a0[e], o);
            a1[e] += __shfl_xor_sync(0xffffffffu, a1[e], o);
        }

    if (lane == 0) {
        float mx = a0[0]; int am = 0;
#pragma unroll
        for (int e = 1; e < NE; ++e) if (a0[e] > mx) { mx = a0[e]; am = e; }
        g_eid[t0] = am;
        atomicAdd(&g_counts[am], 1);
        float mx1 = a1[0]; int am1 = 0;
#pragma unroll
        for (int e = 1; e < NE; ++e) if (a1[e] > mx1) { mx1 = a1[e]; am1 = e; }
        g_eid[t1] = am1;
        atomicAdd(&g_counts[am1], 1);
    }
}

__global__ void build_list_kernel() {
    int t = blockIdx.x * blockDim.x + threadIdx.x;
    if (t >= BTOK) return;
    int e = g_eid[t];
    int p = atomicAdd(&g_fill[e], 1);
    if (p < CAP) { g_list[e * CAP + p] = t; g_keep[t] = 1; }
    else         { g_keep[t] = 0; }
}

// copy x rows only for dropped tokens (none in the typical balanced case)
__global__ void copy_dropped_kernel(const float4* __restrict__ x4, float4* __restrict__ out4) {
    const int warp = threadIdx.x >> 5, lane = threadIdx.x & 31;
    const int t = blockIdx.x * 8 + warp;
    if (g_keep[t]) return;
    const float4* src = x4 + (size_t)t * (D_MODEL / 4);
    float4* dst = out4 + (size_t)t * (D_MODEL / 4);
#pragma unroll
    for (int i = 0; i < 8; ++i) dst[i * 32 + lane] = src[i * 32 + lane];
}

__global__ void stats_kernel(float* __restrict__ out, long long out_size) {
    int e = threadIdx.x;
    float c  = (e < NE) ? (float)g_counts[e] : 0.f;
    const float expc = (float)BTOK / NE;
    float d  = (e < NE) ? (c - expc) * (c - expc) : 0.f;
    float ov = (e < NE) ? fmaxf(c - (float)CAP, 0.f) : 0.f;
#pragma unroll
    for (int o = 16; o > 0; o >>= 1) {
        d  += __shfl_xor_sync(0xffffffffu, d,  o);
        ov += __shfl_xor_sync(0xffffffffu, ov, o);
    }
    if (threadIdx.x == 0) {
        float lb = (d / NE) / (expc * expc);
        if (out_size > (long long)BTOK * D_MODEL)     out[(long long)BTOK * D_MODEL]     = lb;
        if (out_size > (long long)BTOK * D_MODEL + 1) out[(long long)BTOK * D_MODEL + 1] = ov / (float)BTOK;
    }
}

// ---------------- mma helpers ----------------
__device__ __forceinline__ void ldsm4(uint32_t& r0, uint32_t& r1, uint32_t& r2, uint32_t& r3,
                                      const void* p) {
    uint32_t a = (uint32_t)__cvta_generic_to_shared(p);
    asm volatile("ldmatrix.sync.aligned.m8n8.x4.shared.b16 {%0,%1,%2,%3},[%4];"
                 : "=r"(r0), "=r"(r1), "=r"(r2), "=r"(r3) : "r"(a));
}
__device__ __forceinline__ void ldsm4t(uint32_t& r0, uint32_t& r1, uint32_t& r2, uint32_t& r3,
                                       const void* p) {
    uint32_t a = (uint32_t)__cvta_generic_to_shared(p);
    asm volatile("ldmatrix.sync.aligned.m8n8.x4.trans.shared.b16 {%0,%1,%2,%3},[%4];"
                 : "=r"(r0), "=r"(r1), "=r"(r2), "=r"(r3) : "r"(a));
}
__device__ __forceinline__ void mma16816(float* c, const uint32_t* a, const uint32_t* b) {
    asm volatile("mma.sync.aligned.m16n8k16.row.col.f32.f16.f16.f32 "
                 "{%0,%1,%2,%3},{%4,%5,%6,%7},{%8,%9},{%0,%1,%2,%3};"
                 : "+f"(c[0]), "+f"(c[1]), "+f"(c[2]), "+f"(c[3])
                 : "r"(a[0]), "r"(a[1]), "r"(a[2]), "r"(a[3]), "r"(b[0]), "r"(b[1]));
}
__device__ __forceinline__ void cp16(uint32_t dst, const void* src, int sz) {
    asm volatile("cp.async.cg.shared.global [%0], [%1], 16, %2;\n"
                 :: "r"(dst), "l"(src), "r"(sz));
}
__device__ __forceinline__ float gelu_tanh(float v) {
    float v3 = v * v * v;
    return 0.5f * v * (1.f + tanhf(0.7978845608028654f * (v + 0.044715f * v3)));
}

// ---------------- FFN GEMMs (cp.async 4-stage, 128x128 tile, 8 warps, 2 CTAs/SM) ----------------
// MODE 0: H = gelu(gather(g_xh) @ W1[e] + b1) -> g_hbuf (f16)   N=4096 K=1024
// MODE 1: ye = g_hbuf[e] @ W2[e] + b2         -> out (scatter)  N=1024 K=4096
template <int MODE>
__global__ void __launch_bounds__(256, 2) moe_ffn_kernel(const float* __restrict__ bias,
                                                         float* __restrict__ out) {
    constexpr int N  = (MODE == 0) ? D_HIDDEN : D_MODEL;
    constexpr int K  = (MODE == 0) ? D_MODEL  : D_HIDDEN;
    constexpr int NK = K / TK;

    const int e  = blockIdx.z;
    const int m0 = blockIdx.y * TM;
    const int n0 = blockIdx.x * TN;
    const int me = min(g_counts[e], CAP);
    if (m0 >= me) return;

    extern __shared__ char dsm[];
    __shared__ int   s_tok[TM];
    __shared__ float s_bias[TN];

    const int tid = threadIdx.x;
    if (tid < TM) {
        int slot = m0 + tid;
        s_tok[tid] = (slot < me) ? g_list[e * CAP + slot] : -1;
    }
    if (tid < TN) s_bias[tid] = bias[e * N + n0 + tid];
    __syncthreads();

    const __half* Bsrc = ((MODE == 0) ? g_w1h : g_w2h) + (size_t)e * D_MODEL * D_HIDDEN;

    // ---- load geometry (256 threads) ----
    // A tile: 128 rows x 4 chunks(16B) = 512 -> 2 per thread (rows r, r+64)
    const int arow = tid >> 2;              // 0..63
    const int ach  = tid & 3;
    const uint32_t aDst0 = (uint32_t)arow * (SA_HALVES * 2) + (uint32_t)ach * 16;
    const uint32_t aDst1 = aDst0 + (uint32_t)64 * (SA_HALVES * 2);
    const __half* aSrc0;
    const __half* aSrc1;
    int aSz0, aSz1;
    if (MODE == 0) {
        int tok0 = s_tok[arow], tok1 = s_tok[arow + 64];
        aSrc0 = g_xh + ((tok0 >= 0) ? ((size_t)tok0 * D_MODEL) : 0) + ach * 8;
        aSrc1 = g_xh + ((tok1 >= 0) ? ((size_t)tok1 * D_MODEL) : 0) + ach * 8;
        aSz0 = (tok0 >= 0) ? 16 : 0;
        aSz1 = (tok1 >= 0) ? 16 : 0;
    } else {
        aSrc0 = g_hbuf + ((size_t)e * CAP + m0 + arow)      * D_HIDDEN + ach * 8;
        aSrc1 = g_hbuf + ((size_t)e * CAP + m0 + arow + 64) * D_HIDDEN + ach * 8;
        aSz0 = 16; aSz1 = 16;
    }
    // B tile: 32 rows x 16 chunks = 512 -> 2 per thread (rows brow, brow+16)
    const int brow = tid >> 4, bch = tid & 15;
    const __half* bSrc = Bsrc + (size_t)brow * N + n0 + bch * 8;
    const uint32_t bDst = (uint32_t)brow * (SB_HALVES * 2) + (uint32_t)bch * 16;

    uint32_t smemBase = (uint32_t)__cvta_generic_to_shared(dsm);

    auto load_stage = [&](int kt) {
        int s = kt & (NSTG - 1);
        uint32_t aS = smemBase + (uint32_t)s * STG_BYTES;
        uint32_t bS = aS + SA_BYTES;
        int ko = kt * TK;
        cp16(aS + aDst0, aSrc0 + ko, aSz0);
        cp16(aS + aDst1, aSrc1 + ko, aSz1);
        cp16(bS + bDst,                                   bSrc + (size_t)ko * N, 16);
        cp16(bS + bDst + (uint32_t)16 * (SB_HALVES * 2),  bSrc + (size_t)(ko + 16) * N, 16);
        asm volatile("cp.async.commit_group;\n");
    };

#pragma unroll
    for (int kt = 0; kt < NSTG - 1; ++kt) load_stage(kt);

    // ---- compute geometry: 8 warps, warp tile 64 rows x 32 cols ----
    const int wid = tid >> 5, lane = tid & 31;
    const int wr = wid & 1, wc = wid >> 1;              // wr: 0..1, wc: 0..3
    const int lrow = lane & 15, lkh = (lane >> 4) << 3;

    float acc[4][4][4];
#pragma unroll
    for (int mi = 0; mi < 4; ++mi)
#pragma unroll
        for (int nj = 0; nj < 4; ++nj)
#pragma unroll
            for (int q = 0; q < 4; ++q) acc[mi][nj][q] = 0.f;

#pragma unroll 1
    for (int kt = 0; kt < NK; ++kt) {
        asm volatile("cp.async.wait_group %0;\n" :: "n"(NSTG - 2));
        __syncthreads();

        int ktn = kt + NSTG - 1;
        if (ktn < NK) load_stage(ktn);

        const int s = kt & (NSTG - 1);
        const __half* sA = (const __half*)(dsm + (size_t)s * STG_BYTES);
        const __half* sB = (const __half*)(dsm + (size_t)s * STG_BYTES + SA_BYTES);

#pragma unroll
        for (int kk = 0; kk < 2; ++kk) {
            const int ks = kk * 16;
            uint32_t af[4][4];
#pragma unroll
            for (int mi = 0; mi < 4; ++mi)
                ldsm4(af[mi][0], af[mi][1], af[mi][2], af[mi][3],
                      sA + (wr * 64 + mi * 16 + lrow) * SA_HALVES + ks + lkh);
            uint32_t bf[4][2];
#pragma unroll
            for (int nq = 0; nq < 2; ++nq) {
                uint32_t r0, r1, r2, r3;
                ldsm4t(r0, r1, r2, r3,
                       sB + (ks + lrow) * SB_HALVES + wc * 32 + nq * 16 + lkh);
                bf[nq * 2][0] = r0; bf[nq * 2][1] = r1;
                bf[nq * 2 + 1][0] = r2; bf[nq * 2 + 1][1] = r3;
            }
#pragma unroll
            for (int mi = 0; mi < 4; ++mi)
#pragma unroll
                for (int nj = 0; nj < 4; ++nj)
                    mma16816(acc[mi][nj], af[mi], bf[nj]);
        }
    }
    asm volatile("cp.async.wait_group 0;\n");

    // ---- epilogue ----
#pragma unroll
    for (int mi = 0; mi < 4; ++mi) {
        const int r0 = wr * 64 + mi * 16 + (lane >> 2);
#pragma unroll
        for (int nj = 0; nj < 4; ++nj) {
            const int cl = wc * 32 + nj * 8 + (lane & 3) * 2;   // local col in [0,128)
            if (MODE == 0) {
                float bb0 = s_bias[cl], bb1 = s_bias[cl + 1];
                __half* hb = g_hbuf + ((size_t)e * CAP + m0) * D_HIDDEN + n0 + cl;
                float v0 = gelu_tanh(acc[mi][nj][0] + bb0);
                float v1 = gelu_tanh(acc[mi][nj][1] + bb1);
                float v2 = gelu_tanh(acc[mi][nj][2] + bb0);
                float v3 = gelu_tanh(acc[mi][nj][3] + bb1);
                *(__half2*)(hb + (size_t)r0 * D_HIDDEN)       = __floats2half2_rn(v0, v1);
                *(__half2*)(hb + (size_t)(r0 + 8) * D_HIDDEN) = __floats2half2_rn(v2, v3);
            } else {
                float bb0 = s_bias[cl], bb1 = s_bias[cl + 1];
                int tok0 = s_tok[r0], tok1 = s_tok[r0 + 8];
                if (tok0 >= 0) {
                    float2 v; v.x = acc[mi][nj][0] + bb0; v.y = acc[mi][nj][1] + bb1;
                    *(float2*)(out + (size_t)tok0 * D_MODEL + n0 + cl) = v;
                }
                if (tok1 >= 0) {
                    float2 v; v.x = acc[mi][nj][2] + bb0; v.y = acc[mi][nj][3] + bb1;
                    *(float2*)(out + (size_t)tok1 * D_MODEL + n0 + cl) = v;
                }
            }
        }
    }
}

// ---------------- launch ----------------
extern "C" void kernel_launch(void* const* d_in, const int* in_sizes, int n_in,
                              void* d_out, int out_size) {
    const float* x  = (const float*)d_in[0];
    const float* gw = (const float*)d_in[1];
    const float* w1 = (const float*)d_in[2];
    const float* b1 = (const float*)d_in[3];
    const float* w2 = (const float*)d_in[4];
    const float* b2 = (const float*)d_in[5];
    float*       out = (float*)d_out;

    zero_counts_kernel<<<1, 32>>>();
    cvt_w1_kernel<<<2048, 256>>>((const float4*)w1);
    cvt_w2_kernel<<<2048, 256>>>((const float4*)w2);

    cudaFuncSetAttribute(gating_kernel, cudaFuncAttributeMaxDynamicSharedMemorySize, 65536);
    gating_kernel<<<BTOK / 16, 256, 65536>>>((const float4*)x, (const float4*)gw);

    build_list_kernel<<<BTOK / 256, 256>>>();
    stats_kernel<<<1, 32>>>(out, (long long)out_size);
    copy_dropped_kernel<<<BTOK / 8, 256>>>((const float4*)x, (float4*)out);

    cudaFuncSetAttribute(moe_ffn_kernel<0>, cudaFuncAttributeMaxDynamicSharedMemorySize, SMEM_TOTAL);
    cudaFuncSetAttribute(moe_ffn_kernel<1>, cudaFuncAttributeMaxDynamicSharedMemorySize, SMEM_TOTAL);
    moe_ffn_kernel<0><<<dim3(D_HIDDEN / TN, CAP / TM, NE), 256, SMEM_TOTAL>>>(b1, out);
    moe_ffn_kernel<1><<<dim3(D_MODEL / TN, CAP / TM, NE), 256, SMEM_TOTAL>>>(b2, out);
}